// round 14
// baseline (speedup 1.0000x reference)
#include <cuda_runtime.h>
#include <cstdint>

#define HW 65536           // 256*256
#define NB 8
#define NC 32
#define NBC 256

__device__ __align__(16) float g_feat[NB * NC * HW];
__device__ float g_pp[NBC * 4 * 25];
__device__ float g_filt[NBC * 25];

// ---------------------------------------------------------------------------
// Kernel 1: channel mix for ONE batch (R9 shape — measured optimum).
// Warp = 16 och x 64 px, 32 scalar accs; per i-step: 1 LDG.64 +
// 4 LDS.128 (weights, broadcast) + 32 FFMA. ~79 regs, 3 blocks/SM.
// grid = 256, block = 256
// ---------------------------------------------------------------------------
__global__ __launch_bounds__(256) void mix_kernel(
    const float* __restrict__ x,
    const float* __restrict__ w,
    const float* __restrict__ bias,
    int b)
{
    __shared__ float ws[32 * 32];   // [i][o] transposed
    __shared__ float bs[32];

    int tid = threadIdx.x;
    for (int idx = tid; idx < 1024; idx += 256) {
        int i = idx >> 5, o = idx & 31;
        ws[i * 32 + o] = w[o * 32 + i];
    }
    if (tid < 32)
        bs[tid] = bias[tid];
    __syncthreads();

    int wid  = tid >> 5;
    int lane = tid & 31;
    int g = wid & 1;               // och group: g*16 .. g*16+15
    int s = wid >> 1;              // px segment (64 px each)

    size_t pixpair = (size_t)blockIdx.x * 128 + s * 32 + lane;   // float2 idx
    const float2* xp = (const float2*)x + (size_t)b * (NC * (HW / 2)) + pixpair;

    float ax[16], ay[16];
#pragma unroll
    for (int k = 0; k < 16; k++) {
        float bv = bs[g * 16 + k];
        ax[k] = bv;
        ay[k] = bv;
    }

#pragma unroll 8
    for (int i = 0; i < 32; i++) {
        float2 xv = xp[(size_t)i * (HW / 2)];
        const float4* wr = (const float4*)(ws + i * 32 + g * 16);
        float4 w0 = wr[0], w1 = wr[1], w2 = wr[2], w3 = wr[3];
        float wv[16] = {w0.x, w0.y, w0.z, w0.w, w1.x, w1.y, w1.z, w1.w,
                        w2.x, w2.y, w2.z, w2.w, w3.x, w3.y, w3.z, w3.w};
#pragma unroll
        for (int k = 0; k < 16; k++) {
            ax[k] = fmaf(wv[k], xv.x, ax[k]);
            ay[k] = fmaf(wv[k], xv.y, ay[k]);
        }
    }

    float2* fb = (float2*)g_feat + (size_t)b * (NC * (HW / 2)) + pixpair;
#pragma unroll
    for (int k = 0; k < 16; k++)
        fb[(size_t)(g * 16 + k) * (HW / 2)] = make_float2(ax[k], ay[k]);
}

// ---------------------------------------------------------------------------
// Kernel 2: adaptive pool partials on x (commutes with the 1x1 conv).
// Row bins [0,52)[51,103)[102,154)[153,205)[204,256) (overlapping).
// grid = (256, 4 row-chunks), block = 256 (thread = column)
// ---------------------------------------------------------------------------
__global__ __launch_bounds__(256) void pool_kernel(const float* __restrict__ x)
{
    __shared__ float pool[25];
    int bc = blockIdx.x;
    int q  = blockIdx.y;
    int w_ = threadIdx.x;
    if (w_ < 25) pool[w_] = 0.0f;
    __syncthreads();

    const float* img = x + (size_t)bc * HW + (size_t)q * 64 * 256;

    float cs[5] = {0.f, 0.f, 0.f, 0.f, 0.f};
#pragma unroll
    for (int r = 0; r < 64; r++) {
        int h = q * 64 + r;
        float v = img[r * 256 + w_];
        if (h < 52)              cs[0] += v;
        if (h >= 51 && h < 103)  cs[1] += v;
        if (h >= 102 && h < 154) cs[2] += v;
        if (h >= 153 && h < 205) cs[3] += v;
        if (h >= 204)            cs[4] += v;
    }

#pragma unroll
    for (int l = 0; l < 5; l++) {
        int s0 = (l * 256) / 5;
        int e0 = ((l + 1) * 256 + 4) / 5;
        if (w_ >= s0 && w_ < e0) {
#pragma unroll
            for (int k = 0; k < 5; k++)
                if (cs[k] != 0.0f)
                    atomicAdd(&pool[k * 5 + l], cs[k]);
        }
    }
    __syncthreads();
    if (w_ < 25)
        g_pp[(bc * 4 + q) * 25 + w_] = pool[w_];
}

// ---------------------------------------------------------------------------
// Kernel 3: filt[b,o,kl] = bias[o] + sum_i w[o,i] * px[b,i,kl]
// grid = 8, block = 800
// ---------------------------------------------------------------------------
__global__ void filt_kernel(const float* __restrict__ w,
                            const float* __restrict__ bias)
{
    __shared__ float spx[800];
    int b = blockIdx.x;
    int t = threadIdx.x;
    int i  = t / 25;
    int kl = t - i * 25;

    float s = 0.0f;
#pragma unroll
    for (int q = 0; q < 4; q++)
        s += g_pp[((b * 32 + i) * 4 + q) * 25 + kl];
    spx[t] = s * (1.0f / 2704.0f);
    __syncthreads();

    float acc = bias[i];
#pragma unroll
    for (int ic = 0; ic < 32; ic++)
        acc += w[i * 32 + ic] * spx[ic * 25 + kl];
    g_filt[b * 800 + t] = acc;
}

// ---------------------------------------------------------------------------
// Kernel 4: depthwise 5x5 'same' conv for ONE batch (best config: occ 91%).
// grid = (32, 32 channels), block = 256
// ---------------------------------------------------------------------------
__global__ __launch_bounds__(256) void conv_kernel(float* __restrict__ out, int b)
{
    __shared__ float sh[36 * 68];

    int bc  = b * 32 + blockIdx.y;
    int tile = blockIdx.x;
    int tx0 = (tile & 3) * 64;
    int ty0 = (tile >> 2) * 32;

    const float* img = g_feat + (size_t)bc * HW;

    float f[25];
#pragma unroll
    for (int t = 0; t < 25; t++) f[t] = g_filt[bc * 25 + t];

    {
        int c  = threadIdx.x & 63;
        int r0 = threadIdx.x >> 6;
        int gx = tx0 + c - 2;
        bool cin = (unsigned)gx < 256u;
#pragma unroll
        for (int k = 0; k < 9; k++) {
            int r = r0 + k * 4;
            int gy = ty0 + r - 2;
            float v = 0.0f;
            if (cin && (unsigned)gy < 256u)
                v = img[gy * 256 + gx];
            sh[r * 68 + c] = v;
        }
        int c2 = 64 + (threadIdx.x & 3);
        int r2 = threadIdx.x >> 2;
        if (r2 < 36) {
            int gy = ty0 + r2 - 2;
            int gx2 = tx0 + c2 - 2;
            float v = 0.0f;
            if ((unsigned)gy < 256u && (unsigned)gx2 < 256u)
                v = img[gy * 256 + gx2];
            sh[r2 * 68 + c2] = v;
        }
    }
    __syncthreads();

    int x  = threadIdx.x & 63;
    int ys = (threadIdx.x >> 6) * 8;

    float acc[8];
#pragma unroll
    for (int j = 0; j < 8; j++) acc[j] = 0.0f;

#pragma unroll
    for (int r = 0; r < 12; r++) {
        const float* row = sh + (ys + r) * 68 + x;
        float v0 = row[0];
        float v1 = row[1];
        float v2 = row[2];
        float v3 = row[3];
        float v4 = row[4];
#pragma unroll
        for (int ky = 0; ky < 5; ky++) {
            int j = r - ky;
            if (j >= 0 && j < 8) {
                acc[j] += v0 * f[ky * 5 + 0];
                acc[j] += v1 * f[ky * 5 + 1];
                acc[j] += v2 * f[ky * 5 + 2];
                acc[j] += v3 * f[ky * 5 + 3];
                acc[j] += v4 * f[ky * 5 + 4];
            }
        }
    }

    float* op = out + (size_t)bc * HW + (size_t)(ty0 + ys) * 256 + tx0 + x;
#pragma unroll
    for (int j = 0; j < 8; j++)
        op[j * 256] = acc[j];
}

// ---------------------------------------------------------------------------
// Launcher: event-forked multi-stream pipeline (captures into a graph with
// parallel branches — no spinning, exact dependencies):
//   main stream: mix_0 .. mix_7 (back-to-back)
//   s1:          pool -> filt            (independent of mix)
//   s2:          conv_b  after (mix_b event, filt event), b = 0..7
// conv of batch b co-runs with mix of batches b+1..7.
// ---------------------------------------------------------------------------
extern "C" void kernel_launch(void* const* d_in, const int* in_sizes, int n_in,
                              void* d_out, int out_size)
{
    const float* x    = (const float*)d_in[0];   // [8, 32, 256, 256]
    const float* w    = (const float*)d_in[1];   // [32, 32]
    const float* bias = (const float*)d_in[2];   // [32]
    float* out = (float*)d_out;                  // [8, 32, 256, 256]

    static cudaStream_t s1 = nullptr, s2 = nullptr;
    static cudaEvent_t evRoot, evFilt, evMix[NB], evDone;
    if (s1 == nullptr) {
        cudaStreamCreateWithFlags(&s1, cudaStreamNonBlocking);
        cudaStreamCreateWithFlags(&s2, cudaStreamNonBlocking);
        cudaEventCreateWithFlags(&evRoot, cudaEventDisableTiming);
        cudaEventCreateWithFlags(&evFilt, cudaEventDisableTiming);
        for (int b = 0; b < NB; b++)
            cudaEventCreateWithFlags(&evMix[b], cudaEventDisableTiming);
        cudaEventCreateWithFlags(&evDone, cudaEventDisableTiming);
    }

    // fork s1, s2 off the (captured) main stream
    cudaEventRecord(evRoot, 0);
    cudaStreamWaitEvent(s1, evRoot, 0);
    cudaStreamWaitEvent(s2, evRoot, 0);

    // branch s1: pool -> filt
    pool_kernel<<<dim3(NBC, 4), 256, 0, s1>>>(x);
    filt_kernel<<<NB, 800, 0, s1>>>(w, bias);
    cudaEventRecord(evFilt, s1);
    cudaStreamWaitEvent(s2, evFilt, 0);

    // main stream: mix per batch; s2: conv per batch gated on its mix
    for (int b = 0; b < NB; b++) {
        mix_kernel<<<256, 256>>>(x, w, bias, b);
        cudaEventRecord(evMix[b], 0);
        cudaStreamWaitEvent(s2, evMix[b], 0);
        conv_kernel<<<dim3(32, 32), 256, 0, s2>>>(out, b);
    }

    // join: main stream waits for the conv chain
    cudaEventRecord(evDone, s2);
    cudaStreamWaitEvent(0, evDone, 0);
}

// round 15
// speedup vs baseline: 1.1834x; 1.1834x over previous
#include <cuda_runtime.h>
#include <cstdint>

typedef unsigned long long u64;

#define HW 65536           // 256*256
#define NB 8
#define NC 32
#define NBC 256

#define MIX_BLOCKS 2048    // 256 px-chunks x 8 batches (R9 config)
#define POOL_BLOCKS 1024   // 256 (b,c) x 4 row-chunks

__device__ __align__(16) float g_feat[NB * NC * HW];
__device__ float g_pp[NBC * 4 * 25];
__device__ float g_filt[NBC * 25];

__device__ __forceinline__ u64 fma2(u64 a, u64 b, u64 c) {
    u64 d;
    asm("fma.rn.f32x2 %0, %1, %2, %3;" : "=l"(d) : "l"(a), "l"(b), "l"(c));
    return d;
}
__device__ __forceinline__ u64 dup(float f) {
    unsigned u = __float_as_uint(f);
    return ((u64)u << 32) | (u64)u;
}

// ---------------------------------------------------------------------------
// Kernel 1: FUSED channel-mix + adaptive-pool-partials (R9 structure).
// Mix path — SINGLE CHANGE vs R9: packed fma.rn.f32x2 inner loop.
//   Warp = 16 och x 64 px, 16 u64 accs (same 32 regs as R9's 32 floats).
//   Per i-step: 1 LDG.64 + 8 LDS.128 (dup weights, broadcast) + 16 FFMA2
//   (was 4 LDS.128 + 32 FFMA). If FFMA2 is double-rate, fma-pipe time/warp
//   halves (64 -> 32 cyc per i) and issue slots drop 37 -> 25.
// Pool path: unchanged.
// grid = 3072, block = 256
// ---------------------------------------------------------------------------
__global__ __launch_bounds__(256) void mixpool_kernel(
    const float* __restrict__ x,
    const float* __restrict__ w,
    const float* __restrict__ bias)
{
    if (blockIdx.x < MIX_BLOCKS) {
        // ------------------------- mix path -------------------------
        __shared__ u64 wq[32 * 32];     // [i][o] duplicated {w,w}, transposed
        __shared__ u64 b2[32];

        int tid = threadIdx.x;
        for (int idx = tid; idx < 1024; idx += 256) {
            int i = idx >> 5, o = idx & 31;
            wq[i * 32 + o] = dup(w[o * 32 + i]);
        }
        if (tid < 32)
            b2[tid] = dup(bias[tid]);
        __syncthreads();

        int wid  = tid >> 5;
        int lane = tid & 31;
        int g = wid & 1;               // och group: g*16 .. g*16+15
        int s = wid >> 1;              // px segment (64 px each)

        int b  = blockIdx.x >> 8;      // batch
        int cx = blockIdx.x & 255;     // 256-px chunk within image
        size_t pixpair = (size_t)cx * 128 + s * 32 + lane;   // f32x2 idx
        const u64* xp = (const u64*)x + (size_t)b * (NC * (HW / 2)) + pixpair;

        u64 acc[16];
#pragma unroll
        for (int k = 0; k < 16; k++)
            acc[k] = b2[g * 16 + k];

#pragma unroll 8
        for (int i = 0; i < 32; i++) {
            u64 xv = xp[(size_t)i * (HW / 2)];
            const ulonglong2* wr = (const ulonglong2*)(wq + i * 32 + g * 16);
#pragma unroll
            for (int q = 0; q < 8; q++) {
                ulonglong2 wp = wr[q];
                acc[2 * q]     = fma2(wp.x, xv, acc[2 * q]);
                acc[2 * q + 1] = fma2(wp.y, xv, acc[2 * q + 1]);
            }
        }

        u64* fb = (u64*)g_feat + (size_t)b * (NC * (HW / 2)) + pixpair;
#pragma unroll
        for (int k = 0; k < 16; k++)
            fb[(size_t)(g * 16 + k) * (HW / 2)] = acc[k];

    } else {
        // ------------------------- pool path -------------------------
        // Row bins [0,52)[51,103)[102,154)[153,205)[204,256) (overlap).
        __shared__ float pool[25];
        int idx = blockIdx.x - MIX_BLOCKS;
        int bc = idx >> 2;             // (b*32 + channel)
        int q  = idx & 3;              // 64-row chunk
        int w_ = threadIdx.x;          // column
        if (w_ < 25) pool[w_] = 0.0f;
        __syncthreads();

        const float* img = x + (size_t)bc * HW + (size_t)q * 64 * 256;

        float cs[5] = {0.f, 0.f, 0.f, 0.f, 0.f};
#pragma unroll
        for (int r = 0; r < 64; r++) {
            int h = q * 64 + r;
            float v = img[r * 256 + w_];
            if (h < 52)              cs[0] += v;
            if (h >= 51 && h < 103)  cs[1] += v;
            if (h >= 102 && h < 154) cs[2] += v;
            if (h >= 153 && h < 205) cs[3] += v;
            if (h >= 204)            cs[4] += v;
        }

#pragma unroll
        for (int l = 0; l < 5; l++) {
            int s0 = (l * 256) / 5;
            int e0 = ((l + 1) * 256 + 4) / 5;
            if (w_ >= s0 && w_ < e0) {
#pragma unroll
                for (int k = 0; k < 5; k++)
                    if (cs[k] != 0.0f)
                        atomicAdd(&pool[k * 5 + l], cs[k]);
            }
        }
        __syncthreads();
        if (w_ < 25)
            g_pp[(bc * 4 + q) * 25 + w_] = pool[w_];
    }
}

// ---------------------------------------------------------------------------
// Kernel 2: filt[b,o,kl] = bias[o] + sum_i w[o,i] * px[b,i,kl]
// (pooling commutes with the 1x1 conv: pool matrix is row-stochastic)
// grid = 8, block = 800
// ---------------------------------------------------------------------------
__global__ void filt_kernel(const float* __restrict__ w,
                            const float* __restrict__ bias)
{
    __shared__ float spx[800];
    int b = blockIdx.x;
    int t = threadIdx.x;
    int i  = t / 25;
    int kl = t - i * 25;

    float s = 0.0f;
#pragma unroll
    for (int q = 0; q < 4; q++)
        s += g_pp[((b * 32 + i) * 4 + q) * 25 + kl];
    spx[t] = s * (1.0f / 2704.0f);
    __syncthreads();

    float acc = bias[i];
#pragma unroll
    for (int ic = 0; ic < 32; ic++)
        acc += w[i * 32 + ic] * spx[ic * 25 + kl];
    g_filt[b * 800 + t] = acc;
}

// ---------------------------------------------------------------------------
// Kernel 3: depthwise 5x5 'same' conv (best measured config: 38 us,
// occ 91%, issue 70%). 64x32 tile, 36x68 halo, thread = 1 col x 8 rows,
// division-free halo staging. UNCHANGED (control).
// grid = (32, 256), block = 256
// ---------------------------------------------------------------------------
__global__ __launch_bounds__(256) void conv_kernel(float* __restrict__ out)
{
    __shared__ float sh[36 * 68];

    int bc  = blockIdx.y;
    int tile = blockIdx.x;
    int tx0 = (tile & 3) * 64;
    int ty0 = (tile >> 2) * 32;

    const float* img = g_feat + (size_t)bc * HW;

    float f[25];
#pragma unroll
    for (int t = 0; t < 25; t++) f[t] = g_filt[bc * 25 + t];

    {
        int c  = threadIdx.x & 63;
        int r0 = threadIdx.x >> 6;
        int gx = tx0 + c - 2;
        bool cin = (unsigned)gx < 256u;
#pragma unroll
        for (int k = 0; k < 9; k++) {
            int r = r0 + k * 4;
            int gy = ty0 + r - 2;
            float v = 0.0f;
            if (cin && (unsigned)gy < 256u)
                v = img[gy * 256 + gx];
            sh[r * 68 + c] = v;
        }
        int c2 = 64 + (threadIdx.x & 3);
        int r2 = threadIdx.x >> 2;
        if (r2 < 36) {
            int gy = ty0 + r2 - 2;
            int gx2 = tx0 + c2 - 2;
            float v = 0.0f;
            if ((unsigned)gy < 256u && (unsigned)gx2 < 256u)
                v = img[gy * 256 + gx2];
            sh[r2 * 68 + c2] = v;
        }
    }
    __syncthreads();

    int x  = threadIdx.x & 63;
    int ys = (threadIdx.x >> 6) * 8;

    float acc[8];
#pragma unroll
    for (int j = 0; j < 8; j++) acc[j] = 0.0f;

#pragma unroll
    for (int r = 0; r < 12; r++) {
        const float* row = sh + (ys + r) * 68 + x;
        float v0 = row[0];
        float v1 = row[1];
        float v2 = row[2];
        float v3 = row[3];
        float v4 = row[4];
#pragma unroll
        for (int ky = 0; ky < 5; ky++) {
            int j = r - ky;
            if (j >= 0 && j < 8) {
                acc[j] += v0 * f[ky * 5 + 0];
                acc[j] += v1 * f[ky * 5 + 1];
                acc[j] += v2 * f[ky * 5 + 2];
                acc[j] += v3 * f[ky * 5 + 3];
                acc[j] += v4 * f[ky * 5 + 4];
            }
        }
    }

    float* op = out + (size_t)bc * HW + (size_t)(ty0 + ys) * 256 + tx0 + x;
#pragma unroll
    for (int j = 0; j < 8; j++)
        op[j * 256] = acc[j];
}

// ---------------------------------------------------------------------------
extern "C" void kernel_launch(void* const* d_in, const int* in_sizes, int n_in,
                              void* d_out, int out_size)
{
    const float* x    = (const float*)d_in[0];   // [8, 32, 256, 256]
    const float* w    = (const float*)d_in[1];   // [32, 32]
    const float* bias = (const float*)d_in[2];   // [32]
    float* out = (float*)d_out;                  // [8, 32, 256, 256]

    mixpool_kernel<<<MIX_BLOCKS + POOL_BLOCKS, 256>>>(x, w, bias);
    filt_kernel<<<NB, 800>>>(w, bias);
    conv_kernel<<<dim3(32, NBC), 256>>>(out);
}

// round 17
// speedup vs baseline: 1.2809x; 1.0824x over previous
#include <cuda_runtime.h>
#include <cstdint>

typedef unsigned int u32;

#define HW 65536           // 256*256
#define NB 8
#define NC 32
#define NBC 256

#define MIXT_BLOCKS 1024   // 8 batches x 128 chunks (512 px each)
#define POOL_BLOCKS 1024   // 256 (b,c) x 4 row-chunks

__device__ __align__(16) float g_feat[NB * NC * HW];
__device__ float g_pp[NBC * 4 * 25];
__device__ float g_filt[NBC * 25];

__device__ __forceinline__ u32 tf32h(float v) {
    u32 h;
    asm("cvt.rna.tf32.f32 %0, %1;" : "=r"(h) : "f"(v));
    return h;
}

// mma.sync m16n8k8 tf32: D(16x8,f32) += A(16x8,tf32,row) * B(8x8,tf32,col)
__device__ __forceinline__ void mma_tf32(
    float& d0, float& d1, float& d2, float& d3,
    u32 a0, u32 a1, u32 a2, u32 a3, u32 b0, u32 b1)
{
    asm volatile(
        "mma.sync.aligned.m16n8k8.row.col.f32.tf32.tf32.f32 "
        "{%0,%1,%2,%3}, {%4,%5,%6,%7}, {%8,%9}, {%0,%1,%2,%3};"
        : "+f"(d0), "+f"(d1), "+f"(d2), "+f"(d3)
        : "r"(a0), "r"(a1), "r"(a2), "r"(a3), "r"(b0), "r"(b1));
}

#define WS 33   // padded k-row stride for W^T smem (bank-conflict reduction)

// ---------------------------------------------------------------------------
// Kernel 1: FUSED tensor-core (tf32 mma.sync) channel-mix + pool partials.
// Mix blocks [0,1024): block = 512 px, warp = 64 px x 32 och.
//   3-pass tf32 hi/lo split GEMM: per warp 192 mma (tensor pipe), A loaded
//   straight from gmem (sector-perfect), W^T hi/lo staged in SMEM.
//   Fragment layouts per PTX ISA m16n8k8: gid=lane>>2, tig=lane&3;
//   A: (gid,tig)(gid+8,tig)(gid,tig+4)(gid+8,tig+4)  [row=px, col=k]
//   B: (tig,gid)(tig+4,gid)                           [row=k, col=och]
//   D: (gid,2tig)(gid,2tig+1)(gid+8,2tig)(gid+8,2tig+1)
// Pool blocks [1024,2048): pool partials on x (unchanged).
// grid = 2048, block = 256
// ---------------------------------------------------------------------------
__global__ __launch_bounds__(256) void mixpool_kernel(
    const float* __restrict__ x,
    const float* __restrict__ w,
    const float* __restrict__ bias)
{
    __shared__ u32 wsh[32 * WS];   // W^T hi: [k][n], stride 33
    __shared__ u32 wsl[32 * WS];   // W^T lo
    __shared__ float bs[32];
    __shared__ float pool[25];

    int tid = threadIdx.x;

    if (blockIdx.x < MIXT_BLOCKS) {
        // ------------------------- mix path -------------------------
        for (int idx = tid; idx < 1024; idx += 256) {
            int o = idx >> 5, i = idx & 31;          // w[o][i]
            float wv = w[idx];
            u32 h = tf32h(wv);
            u32 l = tf32h(wv - __uint_as_float(h));
            wsh[i * WS + o] = h;                     // [k][n]
            wsl[i * WS + o] = l;
        }
        if (tid < 32) bs[tid] = bias[tid];
        __syncthreads();

        int wid  = tid >> 5;
        int lane = tid & 31;
        int gid = lane >> 2;       // 0..7
        int tig = lane & 3;        // 0..3

        int b     = blockIdx.x >> 7;
        int chunk = blockIdx.x & 127;
        const float* xb = x + (size_t)b * (NC * HW);
        float* fb = g_feat + (size_t)b * (NC * HW);

        // this lane's 8 output-channel bias values (cols n*8+2tig, +1)
        float bv[8];
#pragma unroll
        for (int n = 0; n < 4; n++) {
            bv[n * 2]     = bs[n * 8 + 2 * tig];
            bv[n * 2 + 1] = bs[n * 8 + 2 * tig + 1];
        }

        int px0 = chunk * 512 + wid * 64;

#pragma unroll 1
        for (int t = 0; t < 4; t++) {
            int pt = px0 + t * 16;
            float d[16];               // 4 n-tiles x (c0..c3)
#pragma unroll
            for (int j = 0; j < 16; j++) d[j] = 0.0f;

#pragma unroll
            for (int k = 0; k < 4; k++) {
                int kc = k * 8;
                // A fragment loads (row=px, col=k-chan)
                float v0 = xb[(size_t)(kc + tig)     * HW + pt + gid];
                float v1 = xb[(size_t)(kc + tig)     * HW + pt + gid + 8];
                float v2 = xb[(size_t)(kc + tig + 4) * HW + pt + gid];
                float v3 = xb[(size_t)(kc + tig + 4) * HW + pt + gid + 8];
                u32 ah0 = tf32h(v0), ah1 = tf32h(v1);
                u32 ah2 = tf32h(v2), ah3 = tf32h(v3);
                u32 al0 = tf32h(v0 - __uint_as_float(ah0));
                u32 al1 = tf32h(v1 - __uint_as_float(ah1));
                u32 al2 = tf32h(v2 - __uint_as_float(ah2));
                u32 al3 = tf32h(v3 - __uint_as_float(ah3));

#pragma unroll
                for (int n = 0; n < 4; n++) {
                    int n8 = n * 8 + gid;
                    u32 bh0 = wsh[(kc + tig)     * WS + n8];
                    u32 bh1 = wsh[(kc + tig + 4) * WS + n8];
                    u32 bl0 = wsl[(kc + tig)     * WS + n8];
                    u32 bl1 = wsl[(kc + tig + 4) * WS + n8];
                    float& d0 = d[n * 4 + 0];
                    float& d1 = d[n * 4 + 1];
                    float& d2 = d[n * 4 + 2];
                    float& d3 = d[n * 4 + 3];
                    mma_tf32(d0, d1, d2, d3, ah0, ah1, ah2, ah3, bh0, bh1);
                    mma_tf32(d0, d1, d2, d3, ah0, ah1, ah2, ah3, bl0, bl1);
                    mma_tf32(d0, d1, d2, d3, al0, al1, al2, al3, bh0, bh1);
                }
            }

            // store D + bias: c0/c1 at px row gid, c2/c3 at gid+8
#pragma unroll
            for (int n = 0; n < 4; n++) {
                float* c0p = fb + (size_t)(n * 8 + 2 * tig) * HW + pt + gid;
                float* c1p = c0p + HW;
                c0p[0] = d[n * 4 + 0] + bv[n * 2];
                c1p[0] = d[n * 4 + 1] + bv[n * 2 + 1];
                c0p[8] = d[n * 4 + 2] + bv[n * 2];
                c1p[8] = d[n * 4 + 3] + bv[n * 2 + 1];
            }
        }

    } else {
        // ------------------------- pool path -------------------------
        // Row bins [0,52)[51,103)[102,154)[153,205)[204,256) (overlap).
        int idx = blockIdx.x - MIXT_BLOCKS;
        int bc = idx >> 2;             // (b*32 + channel)
        int q  = idx & 3;              // 64-row chunk
        int w_ = tid;                  // column
        if (w_ < 25) pool[w_] = 0.0f;
        __syncthreads();

        const float* img = x + (size_t)bc * HW + (size_t)q * 64 * 256;

        float cs[5] = {0.f, 0.f, 0.f, 0.f, 0.f};
#pragma unroll
        for (int r = 0; r < 64; r++) {
            int h = q * 64 + r;
            float v = img[r * 256 + w_];
            if (h < 52)              cs[0] += v;
            if (h >= 51 && h < 103)  cs[1] += v;
            if (h >= 102 && h < 154) cs[2] += v;
            if (h >= 153 && h < 205) cs[3] += v;
            if (h >= 204)            cs[4] += v;
        }

#pragma unroll
        for (int l = 0; l < 5; l++) {
            int s0 = (l * 256) / 5;
            int e0 = ((l + 1) * 256 + 4) / 5;
            if (w_ >= s0 && w_ < e0) {
#pragma unroll
                for (int k = 0; k < 5; k++)
                    if (cs[k] != 0.0f)
                        atomicAdd(&pool[k * 5 + l], cs[k]);
            }
        }
        __syncthreads();
        if (w_ < 25)
            g_pp[(bc * 4 + q) * 25 + w_] = pool[w_];
    }
}

// ---------------------------------------------------------------------------
// Kernel 2: filt[b,o,kl] = bias[o] + sum_i w[o,i] * px[b,i,kl]  (fp32 exact)
// grid = 8, block = 800
// ---------------------------------------------------------------------------
__global__ void filt_kernel(const float* __restrict__ w,
                            const float* __restrict__ bias)
{
    __shared__ float spx[800];
    int b = blockIdx.x;
    int t = threadIdx.x;
    int i  = t / 25;
    int kl = t - i * 25;

    float s = 0.0f;
#pragma unroll
    for (int q = 0; q < 4; q++)
        s += g_pp[((b * 32 + i) * 4 + q) * 25 + kl];
    spx[t] = s * (1.0f / 2704.0f);
    __syncthreads();

    float acc = bias[i];
#pragma unroll
    for (int ic = 0; ic < 32; ic++)
        acc += w[i * 32 + ic] * spx[ic * 25 + kl];
    g_filt[b * 800 + t] = acc;
}

// ---------------------------------------------------------------------------
// Kernel 3: depthwise 5x5 'same' conv (measured best: 38 us, occ 91%).
// grid = (32, 256), block = 256
// ---------------------------------------------------------------------------
__global__ __launch_bounds__(256) void conv_kernel(float* __restrict__ out)
{
    __shared__ float sh[36 * 68];

    int bc  = blockIdx.y;
    int tile = blockIdx.x;
    int tx0 = (tile & 3) * 64;
    int ty0 = (tile >> 2) * 32;

    const float* img = g_feat + (size_t)bc * HW;

    float f[25];
#pragma unroll
    for (int t = 0; t < 25; t++) f[t] = g_filt[bc * 25 + t];

    {
        int c  = threadIdx.x & 63;
        int r0 = threadIdx.x >> 6;
        int gx = tx0 + c - 2;
        bool cin = (unsigned)gx < 256u;
#pragma unroll
        for (int k = 0; k < 9; k++) {
            int r = r0 + k * 4;
            int gy = ty0 + r - 2;
            float v = 0.0f;
            if (cin && (unsigned)gy < 256u)
                v = img[gy * 256 + gx];
            sh[r * 68 + c] = v;
        }
        int c2 = 64 + (threadIdx.x & 3);
        int r2 = threadIdx.x >> 2;
        if (r2 < 36) {
            int gy = ty0 + r2 - 2;
            int gx2 = tx0 + c2 - 2;
            float v = 0.0f;
            if ((unsigned)gy < 256u && (unsigned)gx2 < 256u)
                v = img[gy * 256 + gx2];
            sh[r2 * 68 + c2] = v;
        }
    }
    __syncthreads();

    int x  = threadIdx.x & 63;
    int ys = (threadIdx.x >> 6) * 8;

    float acc[8];
#pragma unroll
    for (int j = 0; j < 8; j++) acc[j] = 0.0f;

#pragma unroll
    for (int r = 0; r < 12; r++) {
        const float* row = sh + (ys + r) * 68 + x;
        float v0 = row[0];
        float v1 = row[1];
        float v2 = row[2];
        float v3 = row[3];
        float v4 = row[4];
#pragma unroll
        for (int ky = 0; ky < 5; ky++) {
            int j = r - ky;
            if (j >= 0 && j < 8) {
                acc[j] += v0 * f[ky * 5 + 0];
                acc[j] += v1 * f[ky * 5 + 1];
                acc[j] += v2 * f[ky * 5 + 2];
                acc[j] += v3 * f[ky * 5 + 3];
                acc[j] += v4 * f[ky * 5 + 4];
            }
        }
    }

    float* op = out + (size_t)bc * HW + (size_t)(ty0 + ys) * 256 + tx0 + x;
#pragma unroll
    for (int j = 0; j < 8; j++)
        op[j * 256] = acc[j];
}

// ---------------------------------------------------------------------------
extern "C" void kernel_launch(void* const* d_in, const int* in_sizes, int n_in,
                              void* d_out, int out_size)
{
    const float* x    = (const float*)d_in[0];   // [8, 32, 256, 256]
    const float* w    = (const float*)d_in[1];   // [32, 32]
    const float* bias = (const float*)d_in[2];   // [32]
    float* out = (float*)d_out;                  // [8, 32, 256, 256]

    mixpool_kernel<<<MIXT_BLOCKS + POOL_BLOCKS, 256>>>(x, w, bias);
    filt_kernel<<<NB, 800>>>(w, bias);
    conv_kernel<<<dim3(32, NBC), 256>>>(out);
}